// round 6
// baseline (speedup 1.0000x reference)
#include <cuda_runtime.h>
#include <math.h>

#define Hh 128
#define Ww 128
#define Nn (Hh*Ww)      // 16384
#define Cc 64
#define TT 64           // tokens per tile
#define TILES (Nn/TT)   // 256
#define PB 64           // k_pass blocks per batch
#define BMAX 16

// Deterministic scratch
__device__ float g_part_kv[BMAX*PB*1024];
__device__ float g_part_ks[BMAX*PB*64];
__device__ float g_kvn[BMAX*1024];
__device__ float g_kmean[BMAX*64];
__device__ float2 g_cs[2048];   // [pos 0..127][k 0..15] -> (cos, sin)

#define LN1E4_OVER16 0.57564627324851145f

__device__ __forceinline__ float elu1(float v) { return v > 0.f ? v + 1.f : __expf(v); }

__device__ __forceinline__ unsigned long long pack2(float lo, float hi) {
    unsigned long long r;
    asm("mov.b64 %0, {%1,%2};" : "=l"(r) : "f"(lo), "f"(hi));
    return r;
}
__device__ __forceinline__ float2 unpack2(unsigned long long v) {
    float2 r;
    asm("mov.b64 {%0,%1}, %2;" : "=f"(r.x), "=f"(r.y) : "l"(v));
    return r;
}
__device__ __forceinline__ void fma2(unsigned long long& d, unsigned long long a, unsigned long long b) {
    asm("fma.rn.f32x2 %0, %1, %2, %0;" : "+l"(d) : "l"(a), "l"(b));
}

// ---------------------------------------------------------------------------
__global__ void init_tables() {
    int idx = threadIdx.x + blockIdx.x * 256;
    if (idx < 2048) {
        int pos = idx >> 4, k = idx & 15;
        float theta = expf(-(float)k * LN1E4_OVER16);
        float ang = (float)pos * theta;
        g_cs[idx] = make_float2(cosf(ang), sinf(ang));
    }
}

// ---------------------------------------------------------------------------
// k_pass smem (floats): Wi 4096 | xs 64x68 | ks 64x68   (51200 B)
// ---------------------------------------------------------------------------
__global__ __launch_bounds__(256, 4) void k_pass(const float* __restrict__ x,
                                                 const float* __restrict__ qkw,
                                                 const float* __restrict__ qkb) {
    extern __shared__ float sm[];
    float4* sWi4 = (float4*)sm;
    const ulonglong2* sW2 = (const ulonglong2*)sm;
    float (*xs)[68] = (float (*)[68])(sm + 4096);
    float (*ks)[68] = (float (*)[68])(sm + 8448);

    const int b  = blockIdx.y;
    const int pb = blockIdx.x;
    const int tid = threadIdx.x;

    // W interleaved-granule layout: [c4*64 + (f&3)*16 + (f>>2)] = W[f][c4*4..+3]
    for (int i = tid; i < 1024; i += 256) {
        int f = i >> 4, c4 = i & 15;
        float4 v = *(const float4*)(qkw + (size_t)(64 + f) * 64 + c4 * 4);
        sWi4[c4 * 64 + (f & 3) * 16 + (f >> 2)] = v;
    }

    const int ff = tid & 15;
    const int tt = tid >> 4;
    const int f0 = ff * 4;
    const int tb = tt * 4;

    const int kid0 = (2 * ff) & 15, kid1 = (2 * ff + 1) & 15;
    const bool useH = (ff < 8);

    const float bias0 = qkb[64 + f0 + 0];
    const float bias1 = qkb[64 + f0 + 1];
    const float bias2 = qkb[64 + f0 + 2];
    const float bias3 = qkb[64 + f0 + 3];

    float ksum[4] = {0.f, 0.f, 0.f, 0.f};

    // kv accumulate ownership: 4x4 (d,e) block, 4-way t-split
    const int e4 = (tid & 3) * 4;
    const int d4 = ((tid >> 2) & 3) * 4;
    const int q4 = (tid >> 4) & 3;
    const int hd2 = tid >> 6;
    unsigned long long kvp[4][2] = {};   // [dj][e-pair]

    const float* xb = x + (size_t)b * Nn * Cc;

    for (int tile = pb; tile < TILES; tile += PB) {
        const int token0 = tile * TT;
        __syncthreads();

        for (int i = tid; i < TT * 16; i += 256) {
            int t = i >> 4, c4 = i & 15;
            float4 v = *(const float4*)(xb + (size_t)(token0 + t) * Cc + c4 * 4);
            *(float4*)&xs[t][c4 * 4] = v;
        }
        __syncthreads();

        unsigned long long acc2[4][4] = {};
#pragma unroll
        for (int c4 = 0; c4 < 16; c4++) {
            ulonglong2 a0 = *(const ulonglong2*)&xs[tb + 0][c4 * 4];
            ulonglong2 a1 = *(const ulonglong2*)&xs[tb + 1][c4 * 4];
            ulonglong2 a2 = *(const ulonglong2*)&xs[tb + 2][c4 * 4];
            ulonglong2 a3 = *(const ulonglong2*)&xs[tb + 3][c4 * 4];
            ulonglong2 w0 = sW2[c4 * 64 + 0 * 16 + ff];
            ulonglong2 w1 = sW2[c4 * 64 + 1 * 16 + ff];
            ulonglong2 w2 = sW2[c4 * 64 + 2 * 16 + ff];
            ulonglong2 w3 = sW2[c4 * 64 + 3 * 16 + ff];
            fma2(acc2[0][0], a0.x, w0.x); fma2(acc2[0][0], a0.y, w0.y);
            fma2(acc2[0][1], a0.x, w1.x); fma2(acc2[0][1], a0.y, w1.y);
            fma2(acc2[0][2], a0.x, w2.x); fma2(acc2[0][2], a0.y, w2.y);
            fma2(acc2[0][3], a0.x, w3.x); fma2(acc2[0][3], a0.y, w3.y);
            fma2(acc2[1][0], a1.x, w0.x); fma2(acc2[1][0], a1.y, w0.y);
            fma2(acc2[1][1], a1.x, w1.x); fma2(acc2[1][1], a1.y, w1.y);
            fma2(acc2[1][2], a1.x, w2.x); fma2(acc2[1][2], a1.y, w2.y);
            fma2(acc2[1][3], a1.x, w3.x); fma2(acc2[1][3], a1.y, w3.y);
            fma2(acc2[2][0], a2.x, w0.x); fma2(acc2[2][0], a2.y, w0.y);
            fma2(acc2[2][1], a2.x, w1.x); fma2(acc2[2][1], a2.y, w1.y);
            fma2(acc2[2][2], a2.x, w2.x); fma2(acc2[2][2], a2.y, w2.y);
            fma2(acc2[2][3], a2.x, w3.x); fma2(acc2[2][3], a2.y, w3.y);
            fma2(acc2[3][0], a3.x, w0.x); fma2(acc2[3][0], a3.y, w0.y);
            fma2(acc2[3][1], a3.x, w1.x); fma2(acc2[3][1], a3.y, w1.y);
            fma2(acc2[3][2], a3.x, w2.x); fma2(acc2[3][2], a3.y, w2.y);
            fma2(acc2[3][3], a3.x, w3.x); fma2(acc2[3][3], a3.y, w3.y);
        }
        float acc[4][4];
#pragma unroll
        for (int i = 0; i < 4; i++)
#pragma unroll
            for (int j = 0; j < 4; j++) {
                float2 p = unpack2(acc2[i][j]);
                acc[i][j] = p.x + p.y;
            }

#pragma unroll
        for (int i = 0; i < 4; i++) {
            int token = token0 + tb + i;
            int pos = useH ? (token >> 7) : (token & 127);
            float k0 = elu1(acc[i][0] + bias0);
            float k1 = elu1(acc[i][1] + bias1);
            float k2 = elu1(acc[i][2] + bias2);
            float k3 = elu1(acc[i][3] + bias3);
            ksum[0] += k0; ksum[1] += k1; ksum[2] += k2; ksum[3] += k3;
            float2 cs0 = __ldg(&g_cs[pos * 16 + kid0]);
            float2 cs1 = __ldg(&g_cs[pos * 16 + kid1]);
            float4 kr;
            kr.x = k0 * cs0.x - k1 * cs0.y;
            kr.y = k0 * cs0.y + k1 * cs0.x;
            kr.z = k2 * cs1.x - k3 * cs1.y;
            kr.w = k2 * cs1.y + k3 * cs1.x;
            *(float4*)&ks[tb + i][f0] = kr;
        }
        __syncthreads();

        // kv accumulate (4x4 block, 16 tokens per thread via t-split)
#pragma unroll 4
        for (int t = q4 * 16; t < q4 * 16 + 16; t++) {
            ulonglong2 kk = *(const ulonglong2*)&ks[t][hd2 * 16 + d4];
            ulonglong2 vv = *(const ulonglong2*)&xs[t][hd2 * 16 + e4];
            float2 k01 = unpack2(kk.x), k23 = unpack2(kk.y);
            unsigned long long dk0 = pack2(k01.x, k01.x);
            unsigned long long dk1 = pack2(k01.y, k01.y);
            unsigned long long dk2 = pack2(k23.x, k23.x);
            unsigned long long dk3 = pack2(k23.y, k23.y);
            fma2(kvp[0][0], dk0, vv.x); fma2(kvp[0][1], dk0, vv.y);
            fma2(kvp[1][0], dk1, vv.x); fma2(kvp[1][1], dk1, vv.y);
            fma2(kvp[2][0], dk2, vv.x); fma2(kvp[2][1], dk2, vv.y);
            fma2(kvp[3][0], dk3, vv.x); fma2(kvp[3][1], dk3, vv.y);
        }
    }

    // block-level kv reduction over t-splits (deterministic), reuse ks
    __syncthreads();
    float* kred = &ks[0][0];   // 4096 floats
#pragma unroll
    for (int dj = 0; dj < 4; dj++) {
#pragma unroll
        for (int ep = 0; ep < 2; ep++) {
            float2 v = unpack2(kvp[dj][ep]);
            int entry0 = (hd2 * 16 + d4 + dj) * 16 + e4 + ep * 2;
            kred[entry0 * 4 + q4] = v.x;
            kred[(entry0 + 1) * 4 + q4] = v.y;
        }
    }
    __syncthreads();
    {
        float* pkv = g_part_kv + ((size_t)(b * PB + pb)) * 1024;
#pragma unroll
        for (int k = 0; k < 4; k++) {
            int entry = tid * 4 + k;
            float4 v = *(const float4*)&kred[entry * 4];
            pkv[entry] = (v.x + v.y) + (v.z + v.w);
        }
    }

    // ksum block reduction (deterministic), reuse ks
    __syncthreads();
    float* red = &ks[0][0];
#pragma unroll
    for (int j = 0; j < 4; j++) red[(f0 + j) * 16 + tt] = ksum[j];
    __syncthreads();
    if (tid < 64) {
        float s = 0.f;
#pragma unroll
        for (int g = 0; g < 16; g++) s += red[tid * 16 + g];
        g_part_ks[(size_t)(b * PB + pb) * 64 + tid] = s;
    }
}

// ---------------------------------------------------------------------------
__global__ __launch_bounds__(256) void reduce_pass() {
    const int b = blockIdx.x;
    const int tid = threadIdx.x;
    const float invN = 1.0f / (float)Nn;
    for (int e = tid; e < 1024; e += 256) {
        float s = 0.f;
        for (int p = 0; p < PB; p++) s += g_part_kv[(size_t)(b * PB + p) * 1024 + e];
        g_kvn[b * 1024 + e] = s * invN;
    }
    if (tid < 64) {
        float s = 0.f;
        for (int p = 0; p < PB; p++) s += g_part_ks[(size_t)(b * PB + p) * 64 + tid];
        g_kmean[b * 64 + tid] = s * invN;
    }
}

// ---------------------------------------------------------------------------
// q_pass (R4 design): smem (floats):
//  [0,4160)      Wi (4096) -> later lepe buf (64x65)
//  [4160,8512)   xs 64x68
//  [8512,12864)  qs 64x68  -> later attn buf (64x65)
//  [12864,13888) kv 1024
//  [13888,13952) km 64
//  [13952,15040) szp 64x17
//  [15040,15296) zz 64x4
//  total 15296 floats = 61184 B
// ---------------------------------------------------------------------------
__global__ __launch_bounds__(256, 3) void q_pass(const float* __restrict__ x,
                                                 const float* __restrict__ qkw,
                                                 const float* __restrict__ qkb,
                                                 const float* __restrict__ lw,
                                                 const float* __restrict__ lb,
                                                 float* __restrict__ out) {
    extern __shared__ float sm[];
    float4* sWi4 = (float4*)sm;
    const ulonglong2* sW2 = (const ulonglong2*)sm;
    float* slepe = sm;                                    // 64x65 after GEMM
    float (*xs)[68] = (float (*)[68])(sm + 4160);
    float (*qs)[68] = (float (*)[68])(sm + 8512);
    float* abuf = sm + 8512;                              // 64x65 after readout
    float* skv  = sm + 12864;
    float* skm  = sm + 13888;
    float (*szp)[17] = (float (*)[17])(sm + 13952);
    float* zz   = sm + 15040;

    const int b = blockIdx.y;
    const int tile = blockIdx.x;
    const int tid = threadIdx.x;
    const int token0 = tile * TT;
    const float* xb = x + (size_t)b * Nn * Cc;

    for (int i = tid; i < 1024; i += 256) {
        int f = i >> 4, c4 = i & 15;
        float4 v = *(const float4*)(qkw + (size_t)f * 64 + c4 * 4);
        sWi4[c4 * 64 + (f & 3) * 16 + (f >> 2)] = v;
    }
    for (int i = tid; i < 1024; i += 256) skv[i] = g_kvn[b * 1024 + i];
    if (tid < 64) skm[tid] = g_kmean[b * 64 + tid];
    for (int i = tid; i < TT * 16; i += 256) {
        int t = i >> 4, c4 = i & 15;
        float4 v = *(const float4*)(xb + (size_t)(token0 + t) * Cc + c4 * 4);
        *(float4*)&xs[t][c4 * 4] = v;
    }
    __syncthreads();

    const int ff = tid & 15;
    const int tt = tid >> 4;
    const int f0 = ff * 4;
    const int tb = tt * 4;
    const int kid0 = (2 * ff) & 15, kid1 = (2 * ff + 1) & 15;
    const bool useH = (ff < 8);

    const float bias0 = qkb[f0 + 0];
    const float bias1 = qkb[f0 + 1];
    const float bias2 = qkb[f0 + 2];
    const float bias3 = qkb[f0 + 3];

    unsigned long long acc2[4][4] = {};
#pragma unroll
    for (int c4 = 0; c4 < 16; c4++) {
        ulonglong2 a0 = *(const ulonglong2*)&xs[tb + 0][c4 * 4];
        ulonglong2 a1 = *(const ulonglong2*)&xs[tb + 1][c4 * 4];
        ulonglong2 a2 = *(const ulonglong2*)&xs[tb + 2][c4 * 4];
        ulonglong2 a3 = *(const ulonglong2*)&xs[tb + 3][c4 * 4];
        ulonglong2 w0 = sW2[c4 * 64 + 0 * 16 + ff];
        ulonglong2 w1 = sW2[c4 * 64 + 1 * 16 + ff];
        ulonglong2 w2 = sW2[c4 * 64 + 2 * 16 + ff];
        ulonglong2 w3 = sW2[c4 * 64 + 3 * 16 + ff];
        fma2(acc2[0][0], a0.x, w0.x); fma2(acc2[0][0], a0.y, w0.y);
        fma2(acc2[0][1], a0.x, w1.x); fma2(acc2[0][1], a0.y, w1.y);
        fma2(acc2[0][2], a0.x, w2.x); fma2(acc2[0][2], a0.y, w2.y);
        fma2(acc2[0][3], a0.x, w3.x); fma2(acc2[0][3], a0.y, w3.y);
        fma2(acc2[1][0], a1.x, w0.x); fma2(acc2[1][0], a1.y, w0.y);
        fma2(acc2[1][1], a1.x, w1.x); fma2(acc2[1][1], a1.y, w1.y);
        fma2(acc2[1][2], a1.x, w2.x); fma2(acc2[1][2], a1.y, w2.y);
        fma2(acc2[1][3], a1.x, w3.x); fma2(acc2[1][3], a1.y, w3.y);
        fma2(acc2[2][0], a2.x, w0.x); fma2(acc2[2][0], a2.y, w0.y);
        fma2(acc2[2][1], a2.x, w1.x); fma2(acc2[2][1], a2.y, w1.y);
        fma2(acc2[2][2], a2.x, w2.x); fma2(acc2[2][2], a2.y, w2.y);
        fma2(acc2[2][3], a2.x, w3.x); fma2(acc2[2][3], a2.y, w3.y);
        fma2(acc2[3][0], a3.x, w0.x); fma2(acc2[3][0], a3.y, w0.y);
        fma2(acc2[3][1], a3.x, w1.x); fma2(acc2[3][1], a3.y, w1.y);
        fma2(acc2[3][2], a3.x, w2.x); fma2(acc2[3][2], a3.y, w2.y);
        fma2(acc2[3][3], a3.x, w3.x); fma2(acc2[3][3], a3.y, w3.y);
    }
    float acc[4][4];
#pragma unroll
    for (int i = 0; i < 4; i++)
#pragma unroll
        for (int j = 0; j < 4; j++) {
            float2 p = unpack2(acc2[i][j]);
            acc[i][j] = p.x + p.y;
        }

    const float km0 = skm[f0 + 0], km1 = skm[f0 + 1], km2 = skm[f0 + 2], km3 = skm[f0 + 3];

#pragma unroll
    for (int i = 0; i < 4; i++) {
        int token = token0 + tb + i;
        int pos = useH ? (token >> 7) : (token & 127);
        float q0 = elu1(acc[i][0] + bias0);
        float q1 = elu1(acc[i][1] + bias1);
        float q2 = elu1(acc[i][2] + bias2);
        float q3 = elu1(acc[i][3] + bias3);
        szp[tb + i][ff] = q0 * km0 + q1 * km1 + q2 * km2 + q3 * km3;
        float2 cs0 = __ldg(&g_cs[pos * 16 + kid0]);
        float2 cs1 = __ldg(&g_cs[pos * 16 + kid1]);
        float4 qr;
        qr.x = q0 * cs0.x - q1 * cs0.y;
        qr.y = q0 * cs0.y + q1 * cs0.x;
        qr.z = q2 * cs1.x - q3 * cs1.y;
        qr.w = q2 * cs1.y + q3 * cs1.x;
        *(float4*)&qs[tb + i][f0] = qr;
    }
    __syncthreads();

    // z reduction
    {
        int t = tid & 63, h4 = tid >> 6;
        float s = szp[t][h4 * 4 + 0] + szp[t][h4 * 4 + 1] + szp[t][h4 * 4 + 2] + szp[t][h4 * 4 + 3];
        zz[t * 4 + h4] = 1.0f / (s + 1e-6f);
    }
    __syncthreads();

    // readout: thread = (e 16, tg 2, hd 4, th 2); 16 tokens x 1 e each
    float areg[16];
    int rtbase;
    {
        int e  = tid & 15;
        int tg = (tid >> 4) & 1;
        int hd = (tid >> 5) & 3;
        int th = tid >> 7;
        rtbase = (th * 2 + tg) * 16;
        float kvc[16];
#pragma unroll
        for (int d = 0; d < 16; d++) kvc[d] = skv[hd * 256 + d * 16 + e];
        unsigned long long kv2[8];
#pragma unroll
        for (int p = 0; p < 8; p++) kv2[p] = pack2(kvc[2 * p], kvc[2 * p + 1]);
#pragma unroll
        for (int i = 0; i < 16; i++) {
            int t = rtbase + i;
            ulonglong2 q0 = *(const ulonglong2*)&qs[t][hd * 16 + 0];
            ulonglong2 q1 = *(const ulonglong2*)&qs[t][hd * 16 + 4];
            ulonglong2 q2 = *(const ulonglong2*)&qs[t][hd * 16 + 8];
            ulonglong2 q3 = *(const ulonglong2*)&qs[t][hd * 16 + 12];
            unsigned long long a2 = 0ull;
            fma2(a2, q0.x, kv2[0]); fma2(a2, q0.y, kv2[1]);
            fma2(a2, q1.x, kv2[2]); fma2(a2, q1.y, kv2[3]);
            fma2(a2, q2.x, kv2[4]); fma2(a2, q2.y, kv2[5]);
            fma2(a2, q3.x, kv2[6]); fma2(a2, q3.y, kv2[7]);
            float2 p = unpack2(a2);
            areg[i] = (p.x + p.y) * zz[t * 4 + hd];
        }
    }
    __syncthreads();   // qs reads done; safe to overwrite qs (abuf) and Wi (slepe)
    {
        int e  = tid & 15;
        int hd = (tid >> 5) & 3;
#pragma unroll
        for (int i = 0; i < 16; i++) abuf[(rtbase + i) * 65 + hd * 16 + e] = areg[i];
    }

    // lepe: thread = (ch 64, tg 4), 16 consecutive w each, sliding window
    {
        int ch = tid & 63;
        int tg = tid >> 6;
        float w9[9];
#pragma unroll
        for (int k = 0; k < 9; k++) w9[k] = lw[ch * 9 + k];
        float bias = lb[ch];
        const int hh = token0 >> 7;
        const int ww0 = token0 & 127;
        const int wstart = ww0 + tg * 16;
        const bool hm = hh > 0, hp = hh < (Hh - 1);
        const float* rm = xb + ((size_t)(hh - 1) * Ww) * Cc + ch;
        const float* r0 = xb + ((size_t)hh * Ww) * Cc + ch;
        const float* rp = xb + ((size_t)(hh + 1) * Ww) * Cc + ch;

        float La, Lb2, Lc, Ma, Mb2, Mc, Ra, Rb2, Rc;
        {
            int gw = wstart - 1;
            if ((unsigned)gw < (unsigned)Ww) {
                La = hm ? rm[(size_t)gw * Cc] : 0.f;
                Lb2 = r0[(size_t)gw * Cc];
                Lc = hp ? rp[(size_t)gw * Cc] : 0.f;
            } else { La = Lb2 = Lc = 0.f; }
            gw = wstart;
            Ma = hm ? rm[(size_t)gw * Cc] : 0.f;
            Mb2 = r0[(size_t)gw * Cc];
            Mc = hp ? rp[(size_t)gw * Cc] : 0.f;
        }
#pragma unroll
        for (int j = 0; j < 16; j++) {
            int gw = wstart + j + 1;
            if ((unsigned)gw < (unsigned)Ww) {
                Ra = hm ? rm[(size_t)gw * Cc] : 0.f;
                Rb2 = r0[(size_t)gw * Cc];
                Rc = hp ? rp[(size_t)gw * Cc] : 0.f;
            } else { Ra = Rb2 = Rc = 0.f; }
            float s = bias;
            s = fmaf(w9[0], La, s);  s = fmaf(w9[1], Ma, s);  s = fmaf(w9[2], Ra, s);
            s = fmaf(w9[3], Lb2, s); s = fmaf(w9[4], Mb2, s); s = fmaf(w9[5], Rb2, s);
            s = fmaf(w9[6], Lc, s);  s = fmaf(w9[7], Mc, s);  s = fmaf(w9[8], Rc, s);
            slepe[(tg * 16 + j) * 65 + ch] = s;
            La = Ma; Lb2 = Mb2; Lc = Mc;
            Ma = Ra; Mb2 = Rb2; Mc = Rc;
        }
    }
    __syncthreads();

    // final NCHW write
    {
        int t = tid & 63, hg = tid >> 6;
        int token = token0 + t;
        float* ob = out + (size_t)b * Cc * Nn;
#pragma unroll
        for (int j = 0; j < 16; j++) {
            int ch = hg * 16 + j;
            ob[(size_t)ch * Nn + token] = abuf[t * 65 + ch] + slepe[t * 65 + ch];
        }
    }
}

// ---------------------------------------------------------------------------
extern "C" void kernel_launch(void* const* d_in, const int* in_sizes, int n_in,
                              void* d_out, int out_size) {
    const float* x   = (const float*)d_in[0];
    const float* qkw = (const float*)d_in[3];
    const float* qkb = (const float*)d_in[4];
    const float* lw  = (const float*)d_in[5];
    const float* lb  = (const float*)d_in[6];
    float* out = (float*)d_out;

    int B = in_sizes[0] / (Nn * Cc);
    if (B > BMAX) B = BMAX;

    const int SMEM_K = 12800 * sizeof(float);   // 51200
    const int SMEM_Q = 15296 * sizeof(float);   // 61184

    cudaFuncSetAttribute(k_pass, cudaFuncAttributeMaxDynamicSharedMemorySize, SMEM_K);
    cudaFuncSetAttribute(q_pass, cudaFuncAttributeMaxDynamicSharedMemorySize, SMEM_Q);

    init_tables<<<8, 256>>>();
    k_pass<<<dim3(PB, B), 256, SMEM_K>>>(x, qkw, qkb);
    reduce_pass<<<B, 256>>>();
    q_pass<<<dim3(TILES, B), 256, SMEM_Q>>>(x, qkw, qkb, lw, lb, out);
}

// round 7
// speedup vs baseline: 1.6588x; 1.6588x over previous
#include <cuda_runtime.h>
#include <math.h>

#define Hh 128
#define Ww 128
#define Nn (Hh*Ww)      // 16384
#define Cc 64
#define TT 64           // tokens per tile
#define TILES (Nn/TT)   // 256
#define PB 64           // k_pass blocks per batch
#define BMAX 16

// Deterministic scratch
__device__ float g_part_kv[BMAX*PB*1024];
__device__ float g_part_ks[BMAX*PB*64];
__device__ float g_kvn[BMAX*1024];
__device__ float g_kmean[BMAX*64];
__device__ float2 g_cs[2048];   // [pos 0..127][k 0..15] -> (cos, sin)

#define LN1E4_OVER16 0.57564627324851145f

__device__ __forceinline__ float elu1(float v) { return v > 0.f ? v + 1.f : __expf(v); }

__device__ __forceinline__ unsigned long long pack2(float lo, float hi) {
    unsigned long long r;
    asm("mov.b64 %0, {%1,%2};" : "=l"(r) : "f"(lo), "f"(hi));
    return r;
}
__device__ __forceinline__ float2 unpack2(unsigned long long v) {
    float2 r;
    asm("mov.b64 {%0,%1}, %2;" : "=f"(r.x), "=f"(r.y) : "l"(v));
    return r;
}
__device__ __forceinline__ void fma2(unsigned long long& d, unsigned long long a, unsigned long long b) {
    asm("fma.rn.f32x2 %0, %1, %2, %0;" : "+l"(d) : "l"(a), "l"(b));
}

// ---------------------------------------------------------------------------
__global__ void init_tables() {
    int idx = threadIdx.x + blockIdx.x * 256;
    if (idx < 2048) {
        int pos = idx >> 4, k = idx & 15;
        float theta = expf(-(float)k * LN1E4_OVER16);
        float ang = (float)pos * theta;
        g_cs[idx] = make_float2(cosf(ang), sinf(ang));
    }
}

// ---------------------------------------------------------------------------
// k_pass smem (floats): Wi 4096 | xs 64x68 | ks 64x68   (51200 B)
// ---------------------------------------------------------------------------
__global__ __launch_bounds__(256, 4) void k_pass(const float* __restrict__ x,
                                                 const float* __restrict__ qkw,
                                                 const float* __restrict__ qkb) {
    extern __shared__ float sm[];
    float4* sWi4 = (float4*)sm;
    const ulonglong2* sW2 = (const ulonglong2*)sm;
    float (*xs)[68] = (float (*)[68])(sm + 4096);
    float (*ks)[68] = (float (*)[68])(sm + 8448);

    const int b  = blockIdx.y;
    const int pb = blockIdx.x;
    const int tid = threadIdx.x;

    // W interleaved-granule layout: [c4*64 + (f&3)*16 + (f>>2)] = W[f][c4*4..+3]
    for (int i = tid; i < 1024; i += 256) {
        int f = i >> 4, c4 = i & 15;
        float4 v = *(const float4*)(qkw + (size_t)(64 + f) * 64 + c4 * 4);
        sWi4[c4 * 64 + (f & 3) * 16 + (f >> 2)] = v;
    }

    const int ff = tid & 15;
    const int tt = tid >> 4;
    const int f0 = ff * 4;
    const int tb = tt * 4;

    const int kid0 = (2 * ff) & 15, kid1 = (2 * ff + 1) & 15;
    const bool useH = (ff < 8);

    const float4 bias4 = *(const float4*)(qkb + 64 + f0);

    float ksum[4] = {0.f, 0.f, 0.f, 0.f};

    // kv accumulate ownership: 4x4 (d,e) block, 4-way t-split
    const int e4 = (tid & 3) * 4;
    const int d4 = ((tid >> 2) & 3) * 4;
    const int q4 = (tid >> 4) & 3;
    const int hd2 = tid >> 6;
    unsigned long long kvp[4][2] = {};   // [dj][e-pair]

    const float* xb = x + (size_t)b * Nn * Cc;

    for (int tile = pb; tile < TILES; tile += PB) {
        const int token0 = tile * TT;
        __syncthreads();

        for (int i = tid; i < TT * 16; i += 256) {
            int t = i >> 4, c4 = i & 15;
            float4 v = *(const float4*)(xb + (size_t)(token0 + t) * Cc + c4 * 4);
            *(float4*)&xs[t][c4 * 4] = v;
        }
        __syncthreads();

        unsigned long long acc2[4][4] = {};
#pragma unroll
        for (int c4 = 0; c4 < 16; c4++) {
            ulonglong2 a0 = *(const ulonglong2*)&xs[tb + 0][c4 * 4];
            ulonglong2 a1 = *(const ulonglong2*)&xs[tb + 1][c4 * 4];
            ulonglong2 a2 = *(const ulonglong2*)&xs[tb + 2][c4 * 4];
            ulonglong2 a3 = *(const ulonglong2*)&xs[tb + 3][c4 * 4];
            ulonglong2 w0 = sW2[c4 * 64 + 0 * 16 + ff];
            ulonglong2 w1 = sW2[c4 * 64 + 1 * 16 + ff];
            ulonglong2 w2 = sW2[c4 * 64 + 2 * 16 + ff];
            ulonglong2 w3 = sW2[c4 * 64 + 3 * 16 + ff];
            fma2(acc2[0][0], a0.x, w0.x); fma2(acc2[0][0], a0.y, w0.y);
            fma2(acc2[0][1], a0.x, w1.x); fma2(acc2[0][1], a0.y, w1.y);
            fma2(acc2[0][2], a0.x, w2.x); fma2(acc2[0][2], a0.y, w2.y);
            fma2(acc2[0][3], a0.x, w3.x); fma2(acc2[0][3], a0.y, w3.y);
            fma2(acc2[1][0], a1.x, w0.x); fma2(acc2[1][0], a1.y, w0.y);
            fma2(acc2[1][1], a1.x, w1.x); fma2(acc2[1][1], a1.y, w1.y);
            fma2(acc2[1][2], a1.x, w2.x); fma2(acc2[1][2], a1.y, w2.y);
            fma2(acc2[1][3], a1.x, w3.x); fma2(acc2[1][3], a1.y, w3.y);
            fma2(acc2[2][0], a2.x, w0.x); fma2(acc2[2][0], a2.y, w0.y);
            fma2(acc2[2][1], a2.x, w1.x); fma2(acc2[2][1], a2.y, w1.y);
            fma2(acc2[2][2], a2.x, w2.x); fma2(acc2[2][2], a2.y, w2.y);
            fma2(acc2[2][3], a2.x, w3.x); fma2(acc2[2][3], a2.y, w3.y);
            fma2(acc2[3][0], a3.x, w0.x); fma2(acc2[3][0], a3.y, w0.y);
            fma2(acc2[3][1], a3.x, w1.x); fma2(acc2[3][1], a3.y, w1.y);
            fma2(acc2[3][2], a3.x, w2.x); fma2(acc2[3][2], a3.y, w2.y);
            fma2(acc2[3][3], a3.x, w3.x); fma2(acc2[3][3], a3.y, w3.y);
        }
        float acc[4][4];
#pragma unroll
        for (int i = 0; i < 4; i++)
#pragma unroll
            for (int j = 0; j < 4; j++) {
                float2 p = unpack2(acc2[i][j]);
                acc[i][j] = p.x + p.y;
            }

#pragma unroll
        for (int i = 0; i < 4; i++) {
            int token = token0 + tb + i;
            int pos = useH ? (token >> 7) : (token & 127);
            float k0 = elu1(acc[i][0] + bias4.x);
            float k1 = elu1(acc[i][1] + bias4.y);
            float k2 = elu1(acc[i][2] + bias4.z);
            float k3 = elu1(acc[i][3] + bias4.w);
            ksum[0] += k0; ksum[1] += k1; ksum[2] += k2; ksum[3] += k3;
            float2 cs0 = __ldg(&g_cs[pos * 16 + kid0]);
            float2 cs1 = __ldg(&g_cs[pos * 16 + kid1]);
            float4 kr;
            kr.x = k0 * cs0.x - k1 * cs0.y;
            kr.y = k0 * cs0.y + k1 * cs0.x;
            kr.z = k2 * cs1.x - k3 * cs1.y;
            kr.w = k2 * cs1.y + k3 * cs1.x;
            *(float4*)&ks[tb + i][f0] = kr;
        }
        __syncthreads();

        // kv accumulate (4x4 block, 16 tokens per thread via t-split)
#pragma unroll 4
        for (int t = q4 * 16; t < q4 * 16 + 16; t++) {
            ulonglong2 kk = *(const ulonglong2*)&ks[t][hd2 * 16 + d4];
            ulonglong2 vv = *(const ulonglong2*)&xs[t][hd2 * 16 + e4];
            float2 k01 = unpack2(kk.x), k23 = unpack2(kk.y);
            unsigned long long dk0 = pack2(k01.x, k01.x);
            unsigned long long dk1 = pack2(k01.y, k01.y);
            unsigned long long dk2 = pack2(k23.x, k23.x);
            unsigned long long dk3 = pack2(k23.y, k23.y);
            fma2(kvp[0][0], dk0, vv.x); fma2(kvp[0][1], dk0, vv.y);
            fma2(kvp[1][0], dk1, vv.x); fma2(kvp[1][1], dk1, vv.y);
            fma2(kvp[2][0], dk2, vv.x); fma2(kvp[2][1], dk2, vv.y);
            fma2(kvp[3][0], dk3, vv.x); fma2(kvp[3][1], dk3, vv.y);
        }
    }

    // block-level kv reduction over t-splits (deterministic), reuse ks
    __syncthreads();
    float* kred = &ks[0][0];   // 4096 floats
#pragma unroll
    for (int dj = 0; dj < 4; dj++) {
#pragma unroll
        for (int ep = 0; ep < 2; ep++) {
            float2 v = unpack2(kvp[dj][ep]);
            int entry0 = (hd2 * 16 + d4 + dj) * 16 + e4 + ep * 2;
            kred[entry0 * 4 + q4] = v.x;
            kred[(entry0 + 1) * 4 + q4] = v.y;
        }
    }
    __syncthreads();
    {
        float* pkv = g_part_kv + ((size_t)(b * PB + pb)) * 1024;
#pragma unroll
        for (int k = 0; k < 4; k++) {
            int entry = tid * 4 + k;
            float4 v = *(const float4*)&kred[entry * 4];
            pkv[entry] = (v.x + v.y) + (v.z + v.w);
        }
    }

    // ksum block reduction (deterministic), reuse ks
    __syncthreads();
    float* red = &ks[0][0];
#pragma unroll
    for (int j = 0; j < 4; j++) red[(f0 + j) * 16 + tt] = ksum[j];
    __syncthreads();
    if (tid < 64) {
        float s = 0.f;
#pragma unroll
        for (int g = 0; g < 16; g++) s += red[tid * 16 + g];
        g_part_ks[(size_t)(b * PB + pb) * 64 + tid] = s;
    }
}

// ---------------------------------------------------------------------------
__global__ __launch_bounds__(256) void reduce_pass() {
    const int b = blockIdx.x;
    const int tid = threadIdx.x;
    const float invN = 1.0f / (float)Nn;
    for (int e = tid; e < 1024; e += 256) {
        float s = 0.f;
        for (int p = 0; p < PB; p++) s += g_part_kv[(size_t)(b * PB + p) * 1024 + e];
        g_kvn[b * 1024 + e] = s * invN;
    }
    if (tid < 64) {
        float s = 0.f;
        for (int p = 0; p < PB; p++) s += g_part_ks[(size_t)(b * PB + p) * 64 + tid];
        g_kmean[b * 64 + tid] = s * invN;
    }
}

// ---------------------------------------------------------------------------
// q_pass smem (floats):
//  [0,4160)      Wi (4096) -> later lepe buf (64x65)
//  [4160,8512)   xs 64x68
//  [8512,12864)  qs 64x68  -> later attn buf (64x65)
//  [12864,13888) kv 1024
//  [13888,13952) km 64
//  [13952,14208) zsm 256
//  total 14208 floats = 56832 B   (4 blocks/SM)
// z computed via 4-lane head-group shuffles (no smem reduction).
// ---------------------------------------------------------------------------
__global__ __launch_bounds__(256, 4) void q_pass(const float* __restrict__ x,
                                                 const float* __restrict__ qkw,
                                                 const float* __restrict__ qkb,
                                                 const float* __restrict__ lw,
                                                 const float* __restrict__ lb,
                                                 float* __restrict__ out) {
    extern __shared__ float sm[];
    float4* sWi4 = (float4*)sm;
    const ulonglong2* sW2 = (const ulonglong2*)sm;
    float* slepe = sm;                                    // 64x65 after GEMM
    float (*xs)[68] = (float (*)[68])(sm + 4160);
    float (*qs)[68] = (float (*)[68])(sm + 8512);
    float* abuf = sm + 8512;                              // 64x65 after readout
    float* skv  = sm + 12864;
    float* skm  = sm + 13888;
    float* zsm  = sm + 13952;                             // [token][head] 64x4

    const int b = blockIdx.y;
    const int tile = blockIdx.x;
    const int tid = threadIdx.x;
    const int token0 = tile * TT;
    const float* xb = x + (size_t)b * Nn * Cc;

    for (int i = tid; i < 1024; i += 256) {
        int f = i >> 4, c4 = i & 15;
        float4 v = *(const float4*)(qkw + (size_t)f * 64 + c4 * 4);
        sWi4[c4 * 64 + (f & 3) * 16 + (f >> 2)] = v;
    }
    for (int i = tid; i < 1024; i += 256) skv[i] = g_kvn[b * 1024 + i];
    if (tid < 64) skm[tid] = g_kmean[b * 64 + tid];
    for (int i = tid; i < TT * 16; i += 256) {
        int t = i >> 4, c4 = i & 15;
        float4 v = *(const float4*)(xb + (size_t)(token0 + t) * Cc + c4 * 4);
        *(float4*)&xs[t][c4 * 4] = v;
    }
    __syncthreads();

    const int ff = tid & 15;
    const int tt = tid >> 4;
    const int f0 = ff * 4;
    const int tb = tt * 4;
    const int kid0 = (2 * ff) & 15, kid1 = (2 * ff + 1) & 15;
    const bool useH = (ff < 8);

    const float4 bias4 = *(const float4*)(qkb + f0);

    unsigned long long acc2[4][4] = {};
#pragma unroll
    for (int c4 = 0; c4 < 16; c4++) {
        ulonglong2 a0 = *(const ulonglong2*)&xs[tb + 0][c4 * 4];
        ulonglong2 a1 = *(const ulonglong2*)&xs[tb + 1][c4 * 4];
        ulonglong2 a2 = *(const ulonglong2*)&xs[tb + 2][c4 * 4];
        ulonglong2 a3 = *(const ulonglong2*)&xs[tb + 3][c4 * 4];
        ulonglong2 w0 = sW2[c4 * 64 + 0 * 16 + ff];
        ulonglong2 w1 = sW2[c4 * 64 + 1 * 16 + ff];
        ulonglong2 w2 = sW2[c4 * 64 + 2 * 16 + ff];
        ulonglong2 w3 = sW2[c4 * 64 + 3 * 16 + ff];
        fma2(acc2[0][0], a0.x, w0.x); fma2(acc2[0][0], a0.y, w0.y);
        fma2(acc2[0][1], a0.x, w1.x); fma2(acc2[0][1], a0.y, w1.y);
        fma2(acc2[0][2], a0.x, w2.x); fma2(acc2[0][2], a0.y, w2.y);
        fma2(acc2[0][3], a0.x, w3.x); fma2(acc2[0][3], a0.y, w3.y);
        fma2(acc2[1][0], a1.x, w0.x); fma2(acc2[1][0], a1.y, w0.y);
        fma2(acc2[1][1], a1.x, w1.x); fma2(acc2[1][1], a1.y, w1.y);
        fma2(acc2[1][2], a1.x, w2.x); fma2(acc2[1][2], a1.y, w2.y);
        fma2(acc2[1][3], a1.x, w3.x); fma2(acc2[1][3], a1.y, w3.y);
        fma2(acc2[2][0], a2.x, w0.x); fma2(acc2[2][0], a2.y, w0.y);
        fma2(acc2[2][1], a2.x, w1.x); fma2(acc2[2][1], a2.y, w1.y);
        fma2(acc2[2][2], a2.x, w2.x); fma2(acc2[2][2], a2.y, w2.y);
        fma2(acc2[2][3], a2.x, w3.x); fma2(acc2[2][3], a2.y, w3.y);
        fma2(acc2[3][0], a3.x, w0.x); fma2(acc2[3][0], a3.y, w0.y);
        fma2(acc2[3][1], a3.x, w1.x); fma2(acc2[3][1], a3.y, w1.y);
        fma2(acc2[3][2], a3.x, w2.x); fma2(acc2[3][2], a3.y, w2.y);
        fma2(acc2[3][3], a3.x, w3.x); fma2(acc2[3][3], a3.y, w3.y);
    }
    float acc[4][4];
#pragma unroll
    for (int i = 0; i < 4; i++)
#pragma unroll
        for (int j = 0; j < 4; j++) {
            float2 p = unpack2(acc2[i][j]);
            acc[i][j] = p.x + p.y;
        }

    const float4 kmv4 = *(const float4*)&skm[f0];

#pragma unroll
    for (int i = 0; i < 4; i++) {
        int token = token0 + tb + i;
        int pos = useH ? (token >> 7) : (token & 127);
        float q0 = elu1(acc[i][0] + bias4.x);
        float q1 = elu1(acc[i][1] + bias4.y);
        float q2 = elu1(acc[i][2] + bias4.z);
        float q3 = elu1(acc[i][3] + bias4.w);
        // z: sum over 16 d of this head = 4 lanes (adjacent) x 4 features
        float zp = q0 * kmv4.x + q1 * kmv4.y + q2 * kmv4.z + q3 * kmv4.w;
        zp += __shfl_xor_sync(0xffffffffu, zp, 1);
        zp += __shfl_xor_sync(0xffffffffu, zp, 2);
        if ((ff & 3) == 0) zsm[(tb + i) * 4 + (ff >> 2)] = 1.0f / (zp + 1e-6f);
        float2 cs0 = __ldg(&g_cs[pos * 16 + kid0]);
        float2 cs1 = __ldg(&g_cs[pos * 16 + kid1]);
        float4 qr;
        qr.x = q0 * cs0.x - q1 * cs0.y;
        qr.y = q0 * cs0.y + q1 * cs0.x;
        qr.z = q2 * cs1.x - q3 * cs1.y;
        qr.w = q2 * cs1.y + q3 * cs1.x;
        *(float4*)&qs[tb + i][f0] = qr;
    }
    __syncthreads();

    // readout: thread = (e 16, tg 2, hd 4, th 2); 16 tokens x 1 e each
    float areg[16];
    int rtbase;
    {
        int e  = tid & 15;
        int tg = (tid >> 4) & 1;
        int hd = (tid >> 5) & 3;
        int th = tid >> 7;
        rtbase = (th * 2 + tg) * 16;
        float kvc[16];
#pragma unroll
        for (int d = 0; d < 16; d++) kvc[d] = skv[hd * 256 + d * 16 + e];
        unsigned long long kv2[8];
#pragma unroll
        for (int p = 0; p < 8; p++) kv2[p] = pack2(kvc[2 * p], kvc[2 * p + 1]);
#pragma unroll
        for (int i = 0; i < 16; i++) {
            int t = rtbase + i;
            ulonglong2 q0 = *(const ulonglong2*)&qs[t][hd * 16 + 0];
            ulonglong2 q1 = *(const ulonglong2*)&qs[t][hd * 16 + 4];
            ulonglong2 q2 = *(const ulonglong2*)&qs[t][hd * 16 + 8];
            ulonglong2 q3 = *(const ulonglong2*)&qs[t][hd * 16 + 12];
            unsigned long long a2 = 0ull;
            fma2(a2, q0.x, kv2[0]); fma2(a2, q0.y, kv2[1]);
            fma2(a2, q1.x, kv2[2]); fma2(a2, q1.y, kv2[3]);
            fma2(a2, q2.x, kv2[4]); fma2(a2, q2.y, kv2[5]);
            fma2(a2, q3.x, kv2[6]); fma2(a2, q3.y, kv2[7]);
            float2 p = unpack2(a2);
            areg[i] = (p.x + p.y) * zsm[t * 4 + hd];
        }
    }
    __syncthreads();   // qs reads done; safe to overwrite qs (abuf) and Wi (slepe)
    {
        int e  = tid & 15;
        int hd = (tid >> 5) & 3;
#pragma unroll
        for (int i = 0; i < 16; i++) abuf[(rtbase + i) * 65 + hd * 16 + e] = areg[i];
    }

    // lepe: thread = (ch 64, tg 4), 16 consecutive w each, sliding window
    {
        int ch = tid & 63;
        int tg = tid >> 6;
        float w9[9];
#pragma unroll
        for (int k = 0; k < 9; k++) w9[k] = lw[ch * 9 + k];
        float bias = lb[ch];
        const int hh = token0 >> 7;
        const int ww0 = token0 & 127;
        const int wstart = ww0 + tg * 16;
        const bool hm = hh > 0, hp = hh < (Hh - 1);
        const float* rm = xb + ((size_t)(hh - 1) * Ww) * Cc + ch;
        const float* r0 = xb + ((size_t)hh * Ww) * Cc + ch;
        const float* rp = xb + ((size_t)(hh + 1) * Ww) * Cc + ch;

        float La, Lb2, Lc, Ma, Mb2, Mc, Ra, Rb2, Rc;
        {
            int gw = wstart - 1;
            if ((unsigned)gw < (unsigned)Ww) {
                La = hm ? rm[(size_t)gw * Cc] : 0.f;
                Lb2 = r0[(size_t)gw * Cc];
                Lc = hp ? rp[(size_t)gw * Cc] : 0.f;
            } else { La = Lb2 = Lc = 0.f; }
            gw = wstart;
            Ma = hm ? rm[(size_t)gw * Cc] : 0.f;
            Mb2 = r0[(size_t)gw * Cc];
            Mc = hp ? rp[(size_t)gw * Cc] : 0.f;
        }
#pragma unroll
        for (int j = 0; j < 16; j++) {
            int gw = wstart + j + 1;
            if ((unsigned)gw < (unsigned)Ww) {
                Ra = hm ? rm[(size_t)gw * Cc] : 0.f;
                Rb2 = r0[(size_t)gw * Cc];
                Rc = hp ? rp[(size_t)gw * Cc] : 0.f;
            } else { Ra = Rb2 = Rc = 0.f; }
            float s = bias;
            s = fmaf(w9[0], La, s);  s = fmaf(w9[1], Ma, s);  s = fmaf(w9[2], Ra, s);
            s = fmaf(w9[3], Lb2, s); s = fmaf(w9[4], Mb2, s); s = fmaf(w9[5], Rb2, s);
            s = fmaf(w9[6], Lc, s);  s = fmaf(w9[7], Mc, s);  s = fmaf(w9[8], Rc, s);
            slepe[(tg * 16 + j) * 65 + ch] = s;
            La = Ma; Lb2 = Mb2; Lc = Mc;
            Ma = Ra; Mb2 = Rb2; Mc = Rc;
        }
    }
    __syncthreads();

    // final NCHW write
    {
        int t = tid & 63, hg = tid >> 6;
        int token = token0 + t;
        float* ob = out + (size_t)b * Cc * Nn;
#pragma unroll
        for (int j = 0; j < 16; j++) {
            int ch = hg * 16 + j;
            ob[(size_t)ch * Nn + token] = abuf[t * 65 + ch] + slepe[t * 65 + ch];
        }
    }
}

// ---------------------------------------------------------------------------
extern "C" void kernel_launch(void* const* d_in, const int* in_sizes, int n_in,
                              void* d_out, int out_size) {
    const float* x   = (const float*)d_in[0];
    const float* qkw = (const float*)d_in[3];
    const float* qkb = (const float*)d_in[4];
    const float* lw  = (const float*)d_in[5];
    const float* lb  = (const float*)d_in[6];
    float* out = (float*)d_out;

    int B = in_sizes[0] / (Nn * Cc);
    if (B > BMAX) B = BMAX;

    const int SMEM_K = 12800 * sizeof(float);   // 51200
    const int SMEM_Q = 14208 * sizeof(float);   // 56832

    cudaFuncSetAttribute(k_pass, cudaFuncAttributeMaxDynamicSharedMemorySize, SMEM_K);
    cudaFuncSetAttribute(q_pass, cudaFuncAttributeMaxDynamicSharedMemorySize, SMEM_Q);

    init_tables<<<8, 256>>>();
    k_pass<<<dim3(PB, B), 256, SMEM_K>>>(x, qkw, qkb);
    reduce_pass<<<B, 256>>>();
    q_pass<<<dim3(TILES, B), 256, SMEM_Q>>>(x, qkw, qkb, lw, lb, out);
}